// round 10
// baseline (speedup 1.0000x reference)
#include <cuda_runtime.h>
#include <stdint.h>

// Output: [B, C, X, Y] fp32
#define BB 4
#define CC 256
#define XX 256
#define YY 256
#define XY (XX * YY)
#define GRID (BB * XX * 8)

// Inverse index: dense cell (b,x,y) -> (feature row + 1), 0 = empty. 1 MB.
// Zero-initialized at module load. The LAST sibling block of each (b,x) row
// re-zeroes its slice; g_done / g_fin are reset by the last-finishing block,
// so ALL device state is restored to zero after every launch (deterministic
// across graph replays).
__device__ int d_inv[BB * XX * YY];
__device__ int d_cnt[BB * XX];
__device__ int g_done;   // builder blocks completed
__device__ int g_fin;    // blocks fully finished

// ---------------------------------------------------------------------------
// ONE fused kernel.
//  Phase A (blocks 0..nb-1 only): scatter (point index + 1) into d_inv.
//    512 points/block, coords staged via coalesced int4 loads into smem
//    (reusing the tile4 storage). Publish: per-thread __threadfence, block
//    sync, tid0 atomicAdd(g_done).
//  Gate: tid0 of EVERY block spins (nanosleep backoff) until g_done == nb,
//    fences, then __syncthreads releases the block. Builders are all wave-1
//    resident (nb=391 < ~888 wave-1 slots at 6 blocks/SM), so progress is
//    guaranteed.
//  Phase B (all 8192 blocks): row-locality gather, byte-identical to the
//    proven R8 config (DRAM 71.6%): one block = 256 y cells of one (b,x) row
//    x one 32-channel group; cg fastest -> 8 co-resident siblings cluster
//    reads of each feats row; 1 KB contiguous writes per channel plane.
//    Tile float4[256][8], column swizzle q ^ ((j>>2)&7): conflict-free in
//    the cp.async fill and the store-phase transpose reads.
//  Reset: 8th sibling (via d_cnt) zeroes its inv slice; last block overall
//    (via g_fin) zeroes g_done/g_fin.
// ---------------------------------------------------------------------------
__global__ void __launch_bounds__(256)
fused_kernel(const float* __restrict__ feats,
             const int*   __restrict__ coords,
             float* __restrict__ out, int n, int nb) {
    __shared__ int    s_inv[YY];
    __shared__ int    s_last;
    __shared__ float4 tile4[YY * 8];     // 32 KB (builders reuse as coord stage)

    const int tid = threadIdx.x;
    const int bid = blockIdx.x;

    // ---- Phase A: builders scatter their 512 points ----
    if (bid < nb) {
        int* s_c = reinterpret_cast<int*>(tile4);   // 1536 ints = 6 KB
        const int p0     = bid << 9;                // first point
        const int i4base = (3 * p0) >> 2;           // 1536*bid % 4 == 0
        const int n4     = (3 * n + 3) >> 2;

        #pragma unroll
        for (int k = 0; k < 2; k++) {
            const int s = (k << 8) + tid;           // need 0..383
            if (s < 384) {
                const int i4 = i4base + s;
                int4 v = make_int4(0, 0, 0, 0);
                if (i4 < n4) v = reinterpret_cast<const int4*>(coords)[i4];
                reinterpret_cast<int4*>(s_c)[s] = v;
            }
        }
        __syncthreads();

        #pragma unroll
        for (int e = 0; e < 2; e++) {
            const int p = p0 + (tid << 1) + e;
            if (p < n) {
                const int o = ((tid << 1) + e) * 3;
                const int b = s_c[o + 0];
                const int x = s_c[o + 1];
                const int y = s_c[o + 2];
                if ((unsigned)b < BB && (unsigned)x < XX && (unsigned)y < YY) {
                    d_inv[(b * XX + x) * YY + y] = p + 1;
                }
            }
        }
        __threadfence();                 // publish this thread's scatters
        __syncthreads();                 // whole block done
        if (tid == 0) atomicAdd(&g_done, 1);
    }

    // ---- Gate: wait for ALL builders ----
    if (tid == 0) {
        while (atomicAdd(&g_done, 0) < nb) __nanosleep(128);
        __threadfence();                 // acquire published d_inv
    }
    __syncthreads();

    // ---- Phase B: gather (identical to R8) ----
    const int cg = bid & 7;              // channel group (32 channels)
    const int bx = bid >> 3;             // b*256 + x
    const int b  = bx >> 8;
    const int x  = bx & 255;
    const int L  = bx * YY;

    s_inv[tid] = d_inv[L + tid];
    __syncthreads();                     // all inv loads of this block done

    if (tid == 0) {
        s_last = (atomicAdd(&d_cnt[bx], 1) == 7) ? 1 : 0;
    }

    const int q  = tid & 7;              // 16 B chunk within 128 B
    const int jb = tid >> 3;             // 0..31: cell within wave
    const int csrc = cg * 32 + (q << 2);

    #pragma unroll
    for (int wave = 0; wave < 8; wave++) {
        const int j = (wave << 5) + jb;  // y cell 0..255
        const int r = s_inv[j];
        const float* src = r ? feats + (size_t)(r - 1) * CC + csrc
                             : feats;    // valid addr even when size==0
        const int size = r ? 16 : 0;     // 0 -> zero-fill 16 B
        const uint32_t dst = (uint32_t)__cvta_generic_to_shared(
            &tile4[(j << 3) + (q ^ ((j >> 2) & 7))]);
        asm volatile("cp.async.cg.shared.global [%0], [%1], 16, %2;"
                     :: "r"(dst), "l"(src), "r"(size));
    }
    asm volatile("cp.async.commit_group;");
    asm volatile("cp.async.wait_group 0;");
    __syncthreads();                     // tile ready; s_last visible

    const int w  = tid >> 5;             // warp 0..7 -> channels 4w..4w+3
    const int l  = tid & 31;
    const int l7 = l & 7;
    const int l3 = l >> 3;
    const int colf = ((w ^ l7) << 2) + l3;

    const float* tf = reinterpret_cast<const float*>(tile4);
    float* op = out + ((size_t)b * CC + cg * 32 + (w << 2) + l3) * XY
                    + (size_t)x * YY + (l7 << 2);

    #pragma unroll
    for (int i = 0; i < 8; i++) {
        const int jbase = (i << 5) + (l7 << 2);  // y = 32i + 4*l7
        float4 v;
        v.x = tf[(jbase + 0) * 32 + colf];
        v.y = tf[(jbase + 1) * 32 + colf];
        v.z = tf[(jbase + 2) * 32 + colf];
        v.w = tf[(jbase + 3) * 32 + colf];
        __stcs(reinterpret_cast<float4*>(op + (i << 5)), v);
    }

    // ---- fused resets ----
    if (s_last) {                        // 8th sibling: inv slice + row cnt
        d_inv[L + tid] = 0;
        if (tid == 0) d_cnt[bx] = 0;
    }
    __threadfence();
    if (tid == 0) {
        if (atomicAdd(&g_fin, 1) == GRID - 1) {   // last block overall
            g_done = 0;
            g_fin  = 0;
        }
    }
}

// ---------------------------------------------------------------------------
// Launcher
// ---------------------------------------------------------------------------
extern "C" void kernel_launch(void* const* d_in, const int* in_sizes, int n_in,
                              void* d_out, int out_size) {
    const float* feats  = (const float*)d_in[0];
    const int*   coords = (const int*)d_in[1];
    float*       out    = (float*)d_out;

    const int n  = in_sizes[1] / 3;      // number of sparse points
    const int nb = (n + 511) / 512;      // builder blocks (391 for n=200k)

    fused_kernel<<<GRID, 256>>>(feats, coords, out, n, nb);
}

// round 11
// speedup vs baseline: 1.0004x; 1.0004x over previous
#include <cuda_runtime.h>
#include <stdint.h>

// Output: [B, C, X, Y] fp32
#define BB 4
#define CC 256
#define XX 256
#define YY 256
#define XY (XX * YY)
#define GRID (BB * XX * 8)

// Inverse index: dense cell (b,x,y) -> (feature row + 1), 0 = empty. 1 MB.
// Zero-initialized at module load. The LAST sibling block of each (b,x) row
// re-zeroes its slice; g_done / g_fin are reset by the last-finishing block,
// so ALL device state is restored to zero after every launch (deterministic
// across graph replays).
__device__ int d_inv[BB * XX * YY];
__device__ int d_cnt[BB * XX];
__device__ int g_done;   // builder blocks completed
__device__ int g_fin;    // blocks fully finished

// ---------------------------------------------------------------------------
// ONE fused kernel.
//  Phase A (blocks 0..nb-1 only): scatter (point index + 1) into d_inv.
//    512 points/block, coords staged via coalesced int4 loads into smem
//    (reusing the tile4 storage). Publish: per-thread __threadfence, block
//    sync, tid0 atomicAdd(g_done).
//  Gate: tid0 of EVERY block spins (nanosleep backoff) until g_done == nb,
//    fences, then __syncthreads releases the block. Builders are all wave-1
//    resident (nb=391 < ~888 wave-1 slots at 6 blocks/SM), so progress is
//    guaranteed.
//  Phase B (all 8192 blocks): row-locality gather, byte-identical to the
//    proven R8 config (DRAM 71.6%): one block = 256 y cells of one (b,x) row
//    x one 32-channel group; cg fastest -> 8 co-resident siblings cluster
//    reads of each feats row; 1 KB contiguous writes per channel plane.
//    Tile float4[256][8], column swizzle q ^ ((j>>2)&7): conflict-free in
//    the cp.async fill and the store-phase transpose reads.
//  Reset: 8th sibling (via d_cnt) zeroes its inv slice; last block overall
//    (via g_fin) zeroes g_done/g_fin.
// ---------------------------------------------------------------------------
__global__ void __launch_bounds__(256)
fused_kernel(const float* __restrict__ feats,
             const int*   __restrict__ coords,
             float* __restrict__ out, int n, int nb) {
    __shared__ int    s_inv[YY];
    __shared__ int    s_last;
    __shared__ float4 tile4[YY * 8];     // 32 KB (builders reuse as coord stage)

    const int tid = threadIdx.x;
    const int bid = blockIdx.x;

    // ---- Phase A: builders scatter their 512 points ----
    if (bid < nb) {
        int* s_c = reinterpret_cast<int*>(tile4);   // 1536 ints = 6 KB
        const int p0     = bid << 9;                // first point
        const int i4base = (3 * p0) >> 2;           // 1536*bid % 4 == 0
        const int n4     = (3 * n + 3) >> 2;

        #pragma unroll
        for (int k = 0; k < 2; k++) {
            const int s = (k << 8) + tid;           // need 0..383
            if (s < 384) {
                const int i4 = i4base + s;
                int4 v = make_int4(0, 0, 0, 0);
                if (i4 < n4) v = reinterpret_cast<const int4*>(coords)[i4];
                reinterpret_cast<int4*>(s_c)[s] = v;
            }
        }
        __syncthreads();

        #pragma unroll
        for (int e = 0; e < 2; e++) {
            const int p = p0 + (tid << 1) + e;
            if (p < n) {
                const int o = ((tid << 1) + e) * 3;
                const int b = s_c[o + 0];
                const int x = s_c[o + 1];
                const int y = s_c[o + 2];
                if ((unsigned)b < BB && (unsigned)x < XX && (unsigned)y < YY) {
                    d_inv[(b * XX + x) * YY + y] = p + 1;
                }
            }
        }
        __threadfence();                 // publish this thread's scatters
        __syncthreads();                 // whole block done
        if (tid == 0) atomicAdd(&g_done, 1);
    }

    // ---- Gate: wait for ALL builders ----
    if (tid == 0) {
        while (atomicAdd(&g_done, 0) < nb) __nanosleep(128);
        __threadfence();                 // acquire published d_inv
    }
    __syncthreads();

    // ---- Phase B: gather (identical to R8) ----
    const int cg = bid & 7;              // channel group (32 channels)
    const int bx = bid >> 3;             // b*256 + x
    const int b  = bx >> 8;
    const int x  = bx & 255;
    const int L  = bx * YY;

    s_inv[tid] = d_inv[L + tid];
    __syncthreads();                     // all inv loads of this block done

    if (tid == 0) {
        s_last = (atomicAdd(&d_cnt[bx], 1) == 7) ? 1 : 0;
    }

    const int q  = tid & 7;              // 16 B chunk within 128 B
    const int jb = tid >> 3;             // 0..31: cell within wave
    const int csrc = cg * 32 + (q << 2);

    #pragma unroll
    for (int wave = 0; wave < 8; wave++) {
        const int j = (wave << 5) + jb;  // y cell 0..255
        const int r = s_inv[j];
        const float* src = r ? feats + (size_t)(r - 1) * CC + csrc
                             : feats;    // valid addr even when size==0
        const int size = r ? 16 : 0;     // 0 -> zero-fill 16 B
        const uint32_t dst = (uint32_t)__cvta_generic_to_shared(
            &tile4[(j << 3) + (q ^ ((j >> 2) & 7))]);
        asm volatile("cp.async.cg.shared.global [%0], [%1], 16, %2;"
                     :: "r"(dst), "l"(src), "r"(size));
    }
    asm volatile("cp.async.commit_group;");
    asm volatile("cp.async.wait_group 0;");
    __syncthreads();                     // tile ready; s_last visible

    const int w  = tid >> 5;             // warp 0..7 -> channels 4w..4w+3
    const int l  = tid & 31;
    const int l7 = l & 7;
    const int l3 = l >> 3;
    const int colf = ((w ^ l7) << 2) + l3;

    const float* tf = reinterpret_cast<const float*>(tile4);
    float* op = out + ((size_t)b * CC + cg * 32 + (w << 2) + l3) * XY
                    + (size_t)x * YY + (l7 << 2);

    #pragma unroll
    for (int i = 0; i < 8; i++) {
        const int jbase = (i << 5) + (l7 << 2);  // y = 32i + 4*l7
        float4 v;
        v.x = tf[(jbase + 0) * 32 + colf];
        v.y = tf[(jbase + 1) * 32 + colf];
        v.z = tf[(jbase + 2) * 32 + colf];
        v.w = tf[(jbase + 3) * 32 + colf];
        __stcs(reinterpret_cast<float4*>(op + (i << 5)), v);
    }

    // ---- fused resets ----
    if (s_last) {                        // 8th sibling: inv slice + row cnt
        d_inv[L + tid] = 0;
        if (tid == 0) d_cnt[bx] = 0;
    }
    __threadfence();
    if (tid == 0) {
        if (atomicAdd(&g_fin, 1) == GRID - 1) {   // last block overall
            g_done = 0;
            g_fin  = 0;
        }
    }
}

// ---------------------------------------------------------------------------
// Launcher
// ---------------------------------------------------------------------------
extern "C" void kernel_launch(void* const* d_in, const int* in_sizes, int n_in,
                              void* d_out, int out_size) {
    const float* feats  = (const float*)d_in[0];
    const int*   coords = (const int*)d_in[1];
    float*       out    = (float*)d_out;

    const int n  = in_sizes[1] / 3;      // number of sparse points
    const int nb = (n + 511) / 512;      // builder blocks (391 for n=200k)

    fused_kernel<<<GRID, 256>>>(feats, coords, out, n, nb);
}

// round 12
// speedup vs baseline: 1.0998x; 1.0994x over previous
#include <cuda_runtime.h>
#include <stdint.h>

// Output: [B, C, X, Y] fp32
#define BB 4
#define CC 256
#define XX 256
#define YY 256
#define XY (XX * YY)

// Inverse index: dense cell (b,x,y) -> (feature row + 1), 0 = empty. 1 MB.
// Zero-initialized at module load; the LAST sibling gather block of each
// (b,x) row zeroes its slice again at kernel end, so every launch starts
// from all-zero state. d_cnt likewise returns to zero every launch.
__device__ int d_inv[BB * XX * YY];
__device__ int d_cnt[BB * XX];

// ---------------------------------------------------------------------------
// Kernel 1: scatter (row index + 1) into d_inv. Bounds-guarded = mode="drop".
// 512 points/block, coords staged via fully-coalesced int4 loads.
// ---------------------------------------------------------------------------
__global__ void __launch_bounds__(256)
build_inv_kernel(const int* __restrict__ coords, int n) {
    __shared__ int s_c[1536];            // 512 points * 3 ints = 6 KB

    const int tid = threadIdx.x;
    const int p0  = blockIdx.x << 9;     // first point of this block
    const int i4base = (3 * p0) >> 2;    // int4 offset (1536*blk % 4 == 0)
    const int n4 = (3 * n + 3) >> 2;     // total int4s in coords

    #pragma unroll
    for (int k = 0; k < 2; k++) {
        const int s = (k << 8) + tid;    // need 0..383
        if (s < 384) {
            const int i4 = i4base + s;
            int4 v = make_int4(0, 0, 0, 0);
            if (i4 < n4) v = reinterpret_cast<const int4*>(coords)[i4];
            reinterpret_cast<int4*>(s_c)[s] = v;
        }
    }
    __syncthreads();

    #pragma unroll
    for (int e = 0; e < 2; e++) {
        const int p = p0 + (tid << 1) + e;
        if (p < n) {
            const int o = ((tid << 1) + e) * 3;
            const int b = s_c[o + 0];
            const int x = s_c[o + 1];
            const int y = s_c[o + 2];
            if ((unsigned)b < BB && (unsigned)x < XX && (unsigned)y < YY) {
                d_inv[(b * XX + x) * YY + y] = p + 1;
            }
        }
    }
}

// ---------------------------------------------------------------------------
// Kernel 2: wide row-locality gather with fused inv reset.
// One block = 512 threads: ALL 256 y cells of one (b,x) row x 64 channels
// (channel group cg64, fastest grid dim -> 4 co-resident siblings per row).
// Each feats row is read as 4 x 256 B contiguous chunks (vs 8 x 128 B in the
// previous config) -> half the DRAM read fragmentation. Each block writes
// 1 KB contiguous per channel plane (unchanged, proven optimal).
//
// Tile: float4 tile4[256][16] (64 KB, dynamic); logical (j = y cell,
// q = 16 B chunk of the 64-channel slice) at column q ^ ((j>>2) & 15).
// Store phase: warp w (0..15) owns channels 4w..4w+3; lane l (l7=l&7,
// l3=l>>3) reads rows j = 32i+4*l7+e at float col (w ^ ((8i+l7)&15))*4+l3:
// bank ((w^s)&7)*4+l3 spans all 32 banks -> conflict-free. STG.128, lanes
// contiguous in y -> 4 full 128 B lines per warp-op.
//
// Reset: 4th-arriving sibling (all inv reads done before its arrival point)
// zeroes the 256-entry slice + counter. Deterministic regardless of order.
// ---------------------------------------------------------------------------
__global__ void __launch_bounds__(512)
gather_kernel(const float* __restrict__ feats, float* __restrict__ out) {
    __shared__ int s_inv[YY];
    __shared__ int s_last;
    extern __shared__ float4 tile4[];    // [256 * 16] = 64 KB

    const int cg = blockIdx.x & 3;       // 64-channel group
    const int bx = blockIdx.x >> 2;      // b*256 + x
    const int b  = bx >> 8;
    const int x  = bx & 255;
    const int L  = bx * YY;              // linear cell base of this (b,x) row

    const int tid = threadIdx.x;

    // Stage this row's inverse indices (shared by the 4 sibling blocks).
    if (tid < YY) s_inv[tid] = d_inv[L + tid];
    __syncthreads();                     // all inv loads of this block done

    if (tid == 0) {
        s_last = (atomicAdd(&d_cnt[bx], 1) == 3) ? 1 : 0;
    }

    // ---- load phase: 8 independent cp.async per thread ----
    const int q  = tid & 15;             // 16 B chunk within 256 B
    const int jb = tid >> 4;             // 0..31: cell within wave
    const int csrc = cg * 64 + (q << 2); // first channel of this chunk

    #pragma unroll
    for (int wave = 0; wave < 8; wave++) {
        const int j = (wave << 5) + jb;  // y cell 0..255
        const int r = s_inv[j];
        const float* src = r ? feats + (size_t)(r - 1) * CC + csrc
                             : feats;    // valid addr even when size==0
        const int size = r ? 16 : 0;     // 0 -> zero-fill 16 B
        const uint32_t dst = (uint32_t)__cvta_generic_to_shared(
            &tile4[(j << 4) + (q ^ ((j >> 2) & 15))]);
        asm volatile("cp.async.cg.shared.global [%0], [%1], 16, %2;"
                     :: "r"(dst), "l"(src), "r"(size));
    }
    asm volatile("cp.async.commit_group;");
    asm volatile("cp.async.wait_group 0;");
    __syncthreads();                     // tile ready; s_last visible

    // ---- store phase: 1 KB contiguous per channel, STG.128 full lines ----
    const int w  = tid >> 5;             // warp 0..15 -> channels 4w..4w+3
    const int l  = tid & 31;
    const int l7 = l & 7;
    const int l3 = l >> 3;

    const float* tf = reinterpret_cast<const float*>(tile4);
    float* op = out + ((size_t)b * CC + cg * 64 + (w << 2) + l3) * XY
                    + (size_t)x * YY;

    #pragma unroll
    for (int i = 0; i < 8; i++) {
        const int s    = ((i << 3) + l7) & 15;       // (8i + l7) & 15
        const int colf = ((w ^ s) << 2) + l3;        // float col in 256 B row
        const int jbase = (i << 5) + (l7 << 2);      // y = 32i + 4*l7
        float4 v;
        v.x = tf[(jbase + 0) * 64 + colf];
        v.y = tf[(jbase + 1) * 64 + colf];
        v.z = tf[(jbase + 2) * 64 + colf];
        v.w = tf[(jbase + 3) * 64 + colf];
        __stcs(reinterpret_cast<float4*>(op + jbase), v);
    }

    // ---- fused reset: last sibling restores inv slice + counter to 0 ----
    if (s_last) {
        if (tid < YY) d_inv[L + tid] = 0;
        if (tid == 0) d_cnt[bx] = 0;
    }
}

// ---------------------------------------------------------------------------
// Launcher
// ---------------------------------------------------------------------------
extern "C" void kernel_launch(void* const* d_in, const int* in_sizes, int n_in,
                              void* d_out, int out_size) {
    const float* feats  = (const float*)d_in[0];
    const int*   coords = (const int*)d_in[1];
    float*       out    = (float*)d_out;

    const int n = in_sizes[1] / 3;  // number of sparse points

    const int smem = 256 * 16 * sizeof(float4);   // 64 KB dynamic tile
    cudaFuncSetAttribute(gather_kernel,
                         cudaFuncAttributeMaxDynamicSharedMemorySize, smem);

    build_inv_kernel<<<(n + 511) / 512, 256>>>(coords, n);
    gather_kernel<<<BB * XX * 4, 512, smem>>>(feats, out);
}